// round 3
// baseline (speedup 1.0000x reference)
#include <cuda_runtime.h>
#include <math.h>

// Problem constants
#define FS_F      100.0f
#define N_FILT    12
#define N_CH      27
#define KDIM      5
#define T_IN      65536
#define T_OUT     65532        // T_IN - KDIM + 1
#define TILE      4096
#define THREADS   256
#define GROUPS    4            // 4 groups of (256 threads * 4 outputs) = 4096
#define N_TILES   16           // ceil(T_OUT / TILE)

__global__ __launch_bounds__(THREADS)
void sinc_conv_kernel(const float* __restrict__ x,
                      const float* __restrict__ filt_low,
                      const float* __restrict__ filt_band,
                      float* __restrict__ out)
{
    __shared__ float w[N_FILT][8];   // 5 taps per filter, padded

    const int blk  = blockIdx.x;
    const int tile = blk % N_TILES;
    const int bc   = blk / N_TILES;
    const int c    = bc % N_CH;
    const int b    = bc / N_CH;
    const int tid  = threadIdx.x;

    // ---- build the 12 filters for this channel (threads 0..11) ----
    if (tid < N_FILT) {
        const int f = tid;
        const float PI2 = 6.28318530717958647692f;

        float beg = fabsf(filt_low [c * N_FILT + f]) + 1.0f / FS_F;
        float end = beg + fabsf(filt_band[c * N_FILT + f]);

        // t_right = linspace(1,2,2)/FS = {0.01, 0.02}
        float aE1 = PI2 * FS_F * end * 0.01f;
        float aE2 = PI2 * FS_F * end * 0.02f;
        float aB1 = PI2 * FS_F * beg * 0.01f;
        float aB2 = PI2 * FS_F * beg * 0.02f;
        float yE1 = sinf(aE1) / aE1;
        float yE2 = sinf(aE2) / aE2;
        float yB1 = sinf(aB1) / aB1;
        float yB2 = sinf(aB2) / aB2;

        float e2 = 2.0f * end, b2 = 2.0f * beg;
        float bp0 = e2 * yE2 - b2 * yB2;   // outermost taps (symmetric)
        float bp1 = e2 * yE1 - b2 * yB1;
        float bp2 = e2        - b2;        // center (sinc(0)=1)

        float m = fmaxf(bp2, fmaxf(bp1, bp0));
        float inv_m = 1.0f / m;

        // Blackman-ish window, n = linspace(0, 5, 5) -> n_k = 1.25*k
        float win[KDIM];
        #pragma unroll
        for (int k = 0; k < KDIM; k++) {
            float n = 1.25f * (float)k;
            win[k] = 0.42f - 0.5f * cosf(PI2 * n / 5.0f)
                           + 0.08f * cosf(2.0f * PI2 * n / 5.0f);
        }

        w[f][0] = bp0 * inv_m * win[0];
        w[f][1] = bp1 * inv_m * win[1];
        w[f][2] = bp2 * inv_m * win[2];
        w[f][3] = bp1 * inv_m * win[3];
        w[f][4] = bp0 * inv_m * win[4];
    }
    __syncthreads();

    // hoist filter taps into registers once per block (15 distinct values x 12)
    float cw[N_FILT][KDIM];
    #pragma unroll
    for (int f = 0; f < N_FILT; f++) {
        #pragma unroll
        for (int k = 0; k < KDIM; k++) cw[f][k] = w[f][k];
    }

    const float* xrow  = x + ((size_t)b * N_CH + c) * T_IN;
    float* orow        = out + ((size_t)(b * N_CH + c) * N_FILT) * T_OUT;
    const int tbase    = tile * TILE + tid * 4;

    #pragma unroll
    for (int g = 0; g < GROUPS; g++) {
        const int t0 = tbase + g * (THREADS * 4);
        if (t0 <= T_OUT - 4) {
            const float4 a = __ldg((const float4*)(xrow + t0));
            const float4 d = __ldg((const float4*)(xrow + t0 + 4));
            const float xv0 = a.x, xv1 = a.y, xv2 = a.z, xv3 = a.w;
            const float xv4 = d.x, xv5 = d.y, xv6 = d.z, xv7 = d.w;

            float* obase = orow + t0;
            #pragma unroll
            for (int f = 0; f < N_FILT; f++) {
                const float c0 = cw[f][0], c1 = cw[f][1], c2 = cw[f][2],
                            c3 = cw[f][3], c4 = cw[f][4];
                float4 o;
                o.x = fmaf(xv0, c0, fmaf(xv1, c1, fmaf(xv2, c2, fmaf(xv3, c3, xv4 * c4))));
                o.y = fmaf(xv1, c0, fmaf(xv2, c1, fmaf(xv3, c2, fmaf(xv4, c3, xv5 * c4))));
                o.z = fmaf(xv2, c0, fmaf(xv3, c1, fmaf(xv4, c2, fmaf(xv5, c3, xv6 * c4))));
                o.w = fmaf(xv3, c0, fmaf(xv4, c1, fmaf(xv5, c2, fmaf(xv6, c3, xv7 * c4))));
                *((float4*)(obase + (size_t)f * T_OUT)) = o;
            }
        }
    }
}

extern "C" void kernel_launch(void* const* d_in, const int* in_sizes, int n_in,
                              void* d_out, int out_size)
{
    const float* x         = (const float*)d_in[0];
    const float* filt_low  = (const float*)d_in[1];
    const float* filt_band = (const float*)d_in[2];
    float* out             = (float*)d_out;

    const int grid = 8 * N_CH * N_TILES;  // 3456 blocks, ~6 waves
    sinc_conv_kernel<<<grid, THREADS>>>(x, filt_low, filt_band, out);
}

// round 4
// speedup vs baseline: 1.1293x; 1.1293x over previous
#include <cuda_runtime.h>
#include <math.h>

// Problem constants
#define FS_F      100.0f
#define N_FILT    12
#define N_CH      27
#define KDIM      5
#define T_IN      65536
#define T_OUT     65532        // T_IN - KDIM + 1
#define TILE      2048
#define THREADS   256
#define N_TILES   32           // ceil(T_OUT / TILE)

__global__ __launch_bounds__(THREADS)
void sinc_conv_kernel(const float* __restrict__ x,
                      const float* __restrict__ filt_low,
                      const float* __restrict__ filt_band,
                      float* __restrict__ out)
{
    __shared__ float w[N_FILT][8];   // 5 taps per filter, padded

    const int blk  = blockIdx.x;
    const int tile = blk % N_TILES;
    const int bc   = blk / N_TILES;
    const int c    = bc % N_CH;
    const int b    = bc / N_CH;
    const int tid  = threadIdx.x;

    // ---- build the 12 filters for this channel (threads 0..11) ----
    if (tid < N_FILT) {
        const int f = tid;
        const float PI2 = 6.28318530717958647692f;

        float beg = fabsf(filt_low [c * N_FILT + f]) + 1.0f / FS_F;
        float end = beg + fabsf(filt_band[c * N_FILT + f]);

        // t_right = linspace(1,2,2)/FS = {0.01, 0.02}
        float aE1 = PI2 * FS_F * end * 0.01f;
        float aE2 = PI2 * FS_F * end * 0.02f;
        float aB1 = PI2 * FS_F * beg * 0.01f;
        float aB2 = PI2 * FS_F * beg * 0.02f;
        float yE1 = sinf(aE1) / aE1;
        float yE2 = sinf(aE2) / aE2;
        float yB1 = sinf(aB1) / aB1;
        float yB2 = sinf(aB2) / aB2;

        float e2 = 2.0f * end, b2 = 2.0f * beg;
        float bp0 = e2 * yE2 - b2 * yB2;   // outermost taps (symmetric)
        float bp1 = e2 * yE1 - b2 * yB1;
        float bp2 = e2        - b2;        // center (sinc(0)=1)

        float m = fmaxf(bp2, fmaxf(bp1, bp0));
        float inv_m = 1.0f / m;

        // Blackman-ish window, n = linspace(0, 5, 5) -> n_k = 1.25*k
        float win[KDIM];
        #pragma unroll
        for (int k = 0; k < KDIM; k++) {
            float n = 1.25f * (float)k;
            win[k] = 0.42f - 0.5f * cosf(PI2 * n / 5.0f)
                           + 0.08f * cosf(2.0f * PI2 * n / 5.0f);
        }

        w[f][0] = bp0 * inv_m * win[0];
        w[f][1] = bp1 * inv_m * win[1];
        w[f][2] = bp2 * inv_m * win[2];
        w[f][3] = bp1 * inv_m * win[3];
        w[f][4] = bp0 * inv_m * win[4];
    }
    __syncthreads();

    const float* xrow = x + ((size_t)b * N_CH + c) * T_IN;
    float* orow       = out + ((size_t)(b * N_CH + c) * N_FILT) * T_OUT;

    // two groups of 4 outputs per thread; prefetch ALL input loads first (MLP=4)
    const int t0 = tile * TILE + tid * 4;            // group 0
    const int t1 = t0 + THREADS * 4;                 // group 1

    const bool p0 = (t0 <= T_OUT - 4);
    const bool p1 = (t1 <= T_OUT - 4);

    float4 a0, d0, a1, d1;
    if (p0) { a0 = __ldg((const float4*)(xrow + t0));
              d0 = __ldg((const float4*)(xrow + t0 + 4)); }
    if (p1) { a1 = __ldg((const float4*)(xrow + t1));
              d1 = __ldg((const float4*)(xrow + t1 + 4)); }

    if (p0) {
        const float xv0 = a0.x, xv1 = a0.y, xv2 = a0.z, xv3 = a0.w;
        const float xv4 = d0.x, xv5 = d0.y, xv6 = d0.z, xv7 = d0.w;
        float* obase = orow + t0;
        #pragma unroll
        for (int f = 0; f < N_FILT; f++) {
            const float c0 = w[f][0], c1 = w[f][1], c2 = w[f][2],
                        c3 = w[f][3], c4 = w[f][4];
            float4 o;
            o.x = fmaf(xv0, c0, fmaf(xv1, c1, fmaf(xv2, c2, fmaf(xv3, c3, xv4 * c4))));
            o.y = fmaf(xv1, c0, fmaf(xv2, c1, fmaf(xv3, c2, fmaf(xv4, c3, xv5 * c4))));
            o.z = fmaf(xv2, c0, fmaf(xv3, c1, fmaf(xv4, c2, fmaf(xv5, c3, xv6 * c4))));
            o.w = fmaf(xv3, c0, fmaf(xv4, c1, fmaf(xv5, c2, fmaf(xv6, c3, xv7 * c4))));
            *((float4*)(obase + (size_t)f * T_OUT)) = o;
        }
    }

    if (p1) {
        const float xv0 = a1.x, xv1 = a1.y, xv2 = a1.z, xv3 = a1.w;
        const float xv4 = d1.x, xv5 = d1.y, xv6 = d1.z, xv7 = d1.w;
        float* obase = orow + t1;
        #pragma unroll
        for (int f = 0; f < N_FILT; f++) {
            const float c0 = w[f][0], c1 = w[f][1], c2 = w[f][2],
                        c3 = w[f][3], c4 = w[f][4];
            float4 o;
            o.x = fmaf(xv0, c0, fmaf(xv1, c1, fmaf(xv2, c2, fmaf(xv3, c3, xv4 * c4))));
            o.y = fmaf(xv1, c0, fmaf(xv2, c1, fmaf(xv3, c2, fmaf(xv4, c3, xv5 * c4))));
            o.z = fmaf(xv2, c0, fmaf(xv3, c1, fmaf(xv4, c2, fmaf(xv5, c3, xv6 * c4))));
            o.w = fmaf(xv3, c0, fmaf(xv4, c1, fmaf(xv5, c2, fmaf(xv6, c3, xv7 * c4))));
            *((float4*)(obase + (size_t)f * T_OUT)) = o;
        }
    }
}

extern "C" void kernel_launch(void* const* d_in, const int* in_sizes, int n_in,
                              void* d_out, int out_size)
{
    const float* x         = (const float*)d_in[0];
    const float* filt_low  = (const float*)d_in[1];
    const float* filt_band = (const float*)d_in[2];
    float* out             = (float*)d_out;

    const int grid = 8 * N_CH * N_TILES;  // 6912 blocks, ~12 waves
    sinc_conv_kernel<<<grid, THREADS>>>(x, filt_low, filt_band, out);
}